// round 5
// baseline (speedup 1.0000x reference)
#include <cuda_runtime.h>
#include <cuda_fp16.h>
#include <math.h>
#include <stdint.h>

#define NMAX   100000
#define C      64
#define KTAPS  343
#define TILE_M 128

// ---------------------------------------------------------------------------
// device scratch (no cudaMalloc allowed)
// ---------------------------------------------------------------------------
__device__ __align__(16) __half2 g_xh[(size_t)NMAX * 32];   // x_feat fp16 [N][64]
__device__ __align__(16) __half2 g_w1h[KTAPS * 32];         // W1 fp16 [343][64]
__device__ __align__(16) __half  g_hh[(size_t)NMAX * 64];   // h post-GN fp16 [N][64]
__device__ __align__(16) __half  g_w2t[256 * 64];           // W2^T: [n][k] fp16
__device__ __align__(16) __half  g_w3t[64 * 256];           // W3^T: [c][j] fp16

__device__ __forceinline__ float gelu_exact(float x) {
    return 0.5f * x * (1.f + erff(x * 0.70710678118654752f));
}

// pack two floats -> f16x2 in one uint32
__device__ __forceinline__ uint32_t pack_f16x2(float lo, float hi) {
    uint32_t u;
    asm("cvt.rn.f16x2.f32 %0, %1, %2;" : "=r"(u) : "f"(hi), "f"(lo));
    return u;
}

// D += A * B   (m16n8k16, f16 inputs, f32 accum; A row frag, B col frag)
#define MMA_F16(d, a, b0, b1)                                                           \
    asm volatile("mma.sync.aligned.m16n8k16.row.col.f32.f16.f16.f32 "                   \
                 "{%0,%1,%2,%3}, {%4,%5,%6,%7}, {%8,%9}, {%0,%1,%2,%3};"                \
                 : "+f"((d)[0]), "+f"((d)[1]), "+f"((d)[2]), "+f"((d)[3])               \
                 : "r"((a)[0]), "r"((a)[1]), "r"((a)[2]), "r"((a)[3]),                  \
                   "r"(b0), "r"(b1))

// ---------------------------------------------------------------------------
// Kernel 0: fp16 conversions (x_feat, W1) + transposed fp16 weights (W2^T, W3^T)
// ---------------------------------------------------------------------------
__global__ void prep_kernel(const float* __restrict__ x,
                            const float* __restrict__ W1,
                            const float* __restrict__ W2,
                            const float* __restrict__ W3, int N) {
    int e = blockIdx.x * blockDim.x + threadIdx.x;
    int nx = N * 32;
    if (e < nx) {
        float2 v = ((const float2*)x)[e];
        g_xh[e] = __floats2half2_rn(v.x, v.y);
        return;
    }
    int e1 = e - nx;
    if (e1 < KTAPS * 32) {
        float2 v = ((const float2*)W1)[e1];
        g_w1h[e1] = __floats2half2_rn(v.x, v.y);
        return;
    }
    int e2 = e1 - KTAPS * 32;
    if (e2 < 256 * 32) {                       // g_w2t[n][k] = W2[k][n]
        int n = e2 >> 5, k2 = e2 & 31;
        ((__half2*)g_w2t)[e2] =
            __floats2half2_rn(W2[(2 * k2) * 256 + n], W2[(2 * k2 + 1) * 256 + n]);
        return;
    }
    int e3 = e2 - 256 * 32;
    if (e3 < 64 * 128) {                       // g_w3t[c][j] = W3[j][c]
        int c = e3 >> 7, j2 = e3 & 127;
        ((__half2*)g_w3t)[e3] =
            __floats2half2_rn(W3[(2 * j2) * 64 + c], W3[(2 * j2 + 1) * 64 + c]);
    }
}

// ---------------------------------------------------------------------------
// Kernel 1: depthwise submanifold conv (fp16 gather) + bias + GroupNorm
// one warp per voxel, 2 channels/lane; fp32 accumulation; writes fp16 h
// ---------------------------------------------------------------------------
__global__ void dwconv_gn_kernel(const int*   __restrict__ nbr,
                                 const float* __restrict__ b1,
                                 const float* __restrict__ gamma,
                                 const float* __restrict__ beta,
                                 int N) {
    int gwarp = (blockIdx.x * blockDim.x + threadIdx.x) >> 5;
    int lane  = threadIdx.x & 31;
    if (gwarp >= N) return;
    const int i = gwarp;

    const int* row = nbr + (long long)i * KTAPS;
    float2 acc = make_float2(0.f, 0.f);

    #pragma unroll 1
    for (int kb = 0; kb < KTAPS; kb += 32) {
        int k = kb + lane;
        int idx = (k < KTAPS) ? row[k] : N;
        unsigned m = __ballot_sync(0xffffffffu, idx < N);
        while (m) {
            int j = __ffs(m) - 1;
            m &= m - 1;
            int src = __shfl_sync(0xffffffffu, idx, j);
            __half2 f = g_xh[(size_t)src * 32 + lane];       // 128B warp gather
            __half2 w = g_w1h[(kb + j) * 32 + lane];         // L1-hot
            float2 p = __half22float2(__hmul2(f, w));
            acc.x += p.x; acc.y += p.y;
        }
    }

    float2 bb = ((const float2*)b1)[lane];
    acc.x += bb.x; acc.y += bb.y;

    float s  = acc.x + acc.y;
    float s2 = acc.x * acc.x + acc.y * acc.y;
    #pragma unroll
    for (int o = 16; o > 0; o >>= 1) {
        s  += __shfl_xor_sync(0xffffffffu, s,  o);
        s2 += __shfl_xor_sync(0xffffffffu, s2, o);
    }
    float mu  = s  * (1.f / 64.f);
    float var = s2 * (1.f / 64.f) - mu * mu;
    float inv = rsqrtf(var + 1e-5f);

    float2 g  = ((const float2*)gamma)[lane];
    float2 be = ((const float2*)beta)[lane];
    float ox = (acc.x - mu) * inv * g.x + be.x;
    float oy = (acc.y - mu) * inv * g.y + be.y;

    ((__half2*)g_hh)[(size_t)i * 32 + lane] = __floats2half2_rn(ox, oy);
}

// ---------------------------------------------------------------------------
// Kernel 2: fp16 tensor-core MLP. 128 voxels/CTA, 8 warps (16 rows each).
// Weights via __ldg from L1-resident transposed fp16 images. No shuffles:
// GEMM1 D fragments pack directly into GEMM2 A fragments.
// ---------------------------------------------------------------------------
#define XSTR 72   // smem X row stride in halfs: banks (4g+q) conflict-free

__global__ __launch_bounds__(256)
void mlp_f16_kernel(const float* __restrict__ x_feat,
                    const float* __restrict__ b2,
                    const float* __restrict__ b3,
                    float* __restrict__ out, int N) {
    __shared__ __align__(16) __half sX[TILE_M * XSTR];   // 18 KB
    __shared__ float sB2[256];
    __shared__ float sB3[64];

    const int t  = threadIdx.x;
    const int v0 = blockIdx.x * TILE_M;

    // ---- stage X tile (fp16, zero-pad beyond N) ----
    {
        const uint4* src = (const uint4*)g_hh;
        #pragma unroll
        for (int it = 0; it < 4; ++it) {
            int idx = t + it * 256;             // 0..1023 uint4 (16B = 8 halfs)
            int row = idx >> 3, c8 = idx & 7;
            uint4 v = make_uint4(0, 0, 0, 0);
            if (v0 + row < N) v = src[(size_t)(v0 + row) * 8 + c8];
            *(uint4*)(sX + row * XSTR + c8 * 8) = v;
        }
    }
    sB2[t] = b2[t];
    if (t < 64) sB3[t] = b3[t];
    __syncthreads();

    const int wid = t >> 5, lane = t & 31;
    const int g = lane >> 2, q = lane & 3;
    const int R0 = wid * 16;

    // ---- A fragments of GEMM1 (K=64 -> 4 k-steps of 16), loaded once ----
    uint32_t A1[4][4];
    {
        const __half* xb = sX + (R0 + g) * XSTR + 2 * q;
        #pragma unroll
        for (int ks = 0; ks < 4; ++ks) {
            A1[ks][0] = *(const uint32_t*)(xb + 16 * ks);
            A1[ks][1] = *(const uint32_t*)(xb + 16 * ks + 8 * XSTR);
            A1[ks][2] = *(const uint32_t*)(xb + 16 * ks + 8);
            A1[ks][3] = *(const uint32_t*)(xb + 16 * ks + 8 * XSTR + 8);
        }
    }

    float acc2[8][4];
    #pragma unroll
    for (int n = 0; n < 8; ++n)
        { acc2[n][0] = acc2[n][1] = acc2[n][2] = acc2[n][3] = 0.f; }

    #pragma unroll 1
    for (int ch = 0; ch < 4; ++ch) {
        const int cb = ch * 64;

        // ---- GEMM1 chunk: acc1[16 x 64] ----
        float acc1[8][4];
        #pragma unroll
        for (int n = 0; n < 8; ++n)
            { acc1[n][0] = acc1[n][1] = acc1[n][2] = acc1[n][3] = 0.f; }

        #pragma unroll
        for (int nt = 0; nt < 8; ++nt) {
            const uint32_t* wp = (const uint32_t*)(g_w2t + (cb + nt * 8 + g) * 64) + q;
            #pragma unroll
            for (int ks = 0; ks < 4; ++ks) {
                uint32_t b0 = __ldg(wp + 8 * ks);
                uint32_t b1 = __ldg(wp + 8 * ks + 4);
                MMA_F16(acc1[nt], A1[ks], b0, b1);
            }
        }

        // ---- bias + exact GELU + pack to fp16 (= GEMM2 A fragments) ----
        uint32_t H2[8], H2B[8];
        #pragma unroll
        for (int nt = 0; nt < 8; ++nt) {
            float2 bv = *(const float2*)(sB2 + cb + nt * 8 + 2 * q);
            float g0 = gelu_exact(acc1[nt][0] + bv.x);
            float g1 = gelu_exact(acc1[nt][1] + bv.y);
            float g2 = gelu_exact(acc1[nt][2] + bv.x);
            float g3 = gelu_exact(acc1[nt][3] + bv.y);
            H2[nt]  = pack_f16x2(g0, g1);   // row g,   cols 2q,2q+1
            H2B[nt] = pack_f16x2(g2, g3);   // row g+8
        }

        // ---- GEMM2 partial: acc2 += G_chunk[128x64] @ W3[cb:cb+64, :] ----
        #pragma unroll
        for (int nt2 = 0; nt2 < 8; ++nt2) {
            const uint32_t* wp3 = (const uint32_t*)(g_w3t + (nt2 * 8 + g) * 256 + cb) + q;
            #pragma unroll
            for (int kk = 0; kk < 4; ++kk) {
                uint32_t a[4] = { H2[2 * kk], H2B[2 * kk], H2[2 * kk + 1], H2B[2 * kk + 1] };
                uint32_t b0 = __ldg(wp3 + 8 * kk);
                uint32_t b1 = __ldg(wp3 + 8 * kk + 4);
                MMA_F16(acc2[nt2], a, b0, b1);
            }
        }
    }

    // ---- epilogue: + b3 + residual, store ----
    {
        const int v_lo = v0 + R0 + g;
        const int v_hi = v_lo + 8;
        #pragma unroll
        for (int nt2 = 0; nt2 < 8; ++nt2) {
            int col = nt2 * 8 + 2 * q;
            float2 bv = *(const float2*)(sB3 + col);
            if (v_lo < N) {
                float2 xr = *(const float2*)(x_feat + (size_t)v_lo * 64 + col);
                float2 o;
                o.x = acc2[nt2][0] + bv.x + xr.x;
                o.y = acc2[nt2][1] + bv.y + xr.y;
                *(float2*)(out + (size_t)v_lo * 64 + col) = o;
            }
            if (v_hi < N) {
                float2 xr = *(const float2*)(x_feat + (size_t)v_hi * 64 + col);
                float2 o;
                o.x = acc2[nt2][2] + bv.x + xr.x;
                o.y = acc2[nt2][3] + bv.y + xr.y;
                *(float2*)(out + (size_t)v_hi * 64 + col) = o;
            }
        }
    }
}

// ---------------------------------------------------------------------------
extern "C" void kernel_launch(void* const* d_in, const int* in_sizes, int n_in,
                              void* d_out, int out_size) {
    const float* x_feat = (const float*)d_in[0];
    const int*   nbr    = (const int*)  d_in[1];
    const float* W1     = (const float*)d_in[2];
    const float* b1     = (const float*)d_in[3];
    const float* gamma  = (const float*)d_in[4];
    const float* beta   = (const float*)d_in[5];
    const float* W2     = (const float*)d_in[6];
    const float* b2     = (const float*)d_in[7];
    const float* W3     = (const float*)d_in[8];
    const float* b3     = (const float*)d_in[9];
    float* out = (float*)d_out;

    int N = in_sizes[0] / C;
    int tiles = (N + TILE_M - 1) / TILE_M;

    int prep_elems = N * 32 + KTAPS * 32 + 256 * 32 + 64 * 128;
    prep_kernel<<<(prep_elems + 255) / 256, 256>>>(x_feat, W1, W2, W3, N);

    int blocks1 = (N + 7) / 8;
    dwconv_gn_kernel<<<blocks1, 256>>>(nbr, b1, gamma, beta, N);

    mlp_f16_kernel<<<tiles, 256>>>(x_feat, b2, b3, out, N);
}

// round 6
// speedup vs baseline: 1.6384x; 1.6384x over previous
#include <cuda_runtime.h>
#include <cuda_fp16.h>
#include <math.h>
#include <stdint.h>

#define NMAX   100000
#define C      64
#define KTAPS  343
#define TILE_M 128

// ---------------------------------------------------------------------------
// device scratch (no cudaMalloc allowed)
// ---------------------------------------------------------------------------
__device__ __align__(16) __half2 g_xh[(size_t)(NMAX + 1) * 32]; // x_feat fp16 [N+1][64], row N = zeros
__device__ __align__(16) __half2 g_w1h[KTAPS * 32];             // W1 fp16 [343][64]
__device__ __align__(16) __half  g_hh[(size_t)NMAX * 64];       // h post-GN fp16 [N][64]
__device__ __align__(16) __half  g_w2t[256 * 64];               // W2^T: [n][k] fp16
__device__ __align__(16) __half  g_w3t[64 * 256];               // W3^T: [c][j] fp16

__device__ __forceinline__ float gelu_exact(float x) {
    return 0.5f * x * (1.f + erff(x * 0.70710678118654752f));
}
__device__ __forceinline__ uint32_t pack_f16x2(float lo, float hi) {
    uint32_t u;
    asm("cvt.rn.f16x2.f32 %0, %1, %2;" : "=r"(u) : "f"(hi), "f"(lo));
    return u;
}

// D += A * B   (m16n8k16, f16 inputs, f32 accum; A row frag, B col frag)
#define MMA_F16(d, a, b0, b1)                                                           \
    asm volatile("mma.sync.aligned.m16n8k16.row.col.f32.f16.f16.f32 "                   \
                 "{%0,%1,%2,%3}, {%4,%5,%6,%7}, {%8,%9}, {%0,%1,%2,%3};"                \
                 : "+f"((d)[0]), "+f"((d)[1]), "+f"((d)[2]), "+f"((d)[3])               \
                 : "r"((a)[0]), "r"((a)[1]), "r"((a)[2]), "r"((a)[3]),                  \
                   "r"(b0), "r"(b1))

// ---------------------------------------------------------------------------
// Kernel 0: fp16 conversions + transposed fp16 weights + zero sentinel row
// ---------------------------------------------------------------------------
__global__ void prep_kernel(const float* __restrict__ x,
                            const float* __restrict__ W1,
                            const float* __restrict__ W2,
                            const float* __restrict__ W3, int N) {
    int e = blockIdx.x * blockDim.x + threadIdx.x;
    int nx = (N + 1) * 32;
    if (e < nx) {
        if ((e >> 5) < N) {
            float2 v = ((const float2*)x)[e];
            g_xh[e] = __floats2half2_rn(v.x, v.y);
        } else {
            g_xh[e] = __floats2half2_rn(0.f, 0.f);   // sentinel row N = zeros
        }
        return;
    }
    int e1 = e - nx;
    if (e1 < KTAPS * 32) {
        float2 v = ((const float2*)W1)[e1];
        g_w1h[e1] = __floats2half2_rn(v.x, v.y);
        return;
    }
    int e2 = e1 - KTAPS * 32;
    if (e2 < 256 * 32) {                       // g_w2t[n][k] = W2[k][n]
        int n = e2 >> 5, k2 = e2 & 31;
        ((__half2*)g_w2t)[e2] =
            __floats2half2_rn(W2[(2 * k2) * 256 + n], W2[(2 * k2 + 1) * 256 + n]);
        return;
    }
    int e3 = e2 - 256 * 32;
    if (e3 < 64 * 128) {                       // g_w3t[c][j] = W3[j][c]
        int c = e3 >> 7, j2 = e3 & 127;
        ((__half2*)g_w3t)[e3] =
            __floats2half2_rn(W3[(2 * j2) * 64 + c], W3[(2 * j2 + 1) * 64 + c]);
    }
}

// ---------------------------------------------------------------------------
// Kernel 1: depthwise submanifold conv + bias + GroupNorm
// one warp per voxel; warp-compacted valid-tap list, gather loop unrolled x4
// ---------------------------------------------------------------------------
#define DW_WARPS 8

__global__ __launch_bounds__(256)
void dwconv_gn_kernel(const int*   __restrict__ nbr,
                      const float* __restrict__ b1,
                      const float* __restrict__ gamma,
                      const float* __restrict__ beta,
                      int N) {
    __shared__ int s_list[DW_WARPS][352];

    const int wslot = threadIdx.x >> 5;
    const int lane  = threadIdx.x & 31;
    const int i = blockIdx.x * DW_WARPS + wslot;
    if (i >= N) return;

    const int* row = nbr + (long long)i * KTAPS;
    int* list = s_list[wslot];

    // ---- phase 1: compact valid (src, tap) into smem list ----
    int cnt = 0;
    #pragma unroll
    for (int kb = 0; kb < 352; kb += 32) {
        int k = kb + lane;
        int idx = (k < KTAPS) ? row[k] : N;
        bool valid = idx < N;
        unsigned m = __ballot_sync(0xffffffffu, valid);
        if (valid) {
            int pos = cnt + __popc(m & ((1u << lane) - 1));
            list[pos] = (idx << 9) | k;
        }
        cnt += __popc(m);
    }
    int cnt4 = (cnt + 3) & ~3;
    if (lane < cnt4 - cnt) list[cnt + lane] = (N << 9);   // pad: zero row, tap 0
    __syncwarp();

    // ---- phase 2: unrolled gather-MAC over compacted list ----
    float2 acc = make_float2(0.f, 0.f);
    #pragma unroll 1
    for (int c = 0; c < cnt4; c += 4) {
        int e0 = list[c + 0], e1 = list[c + 1], e2 = list[c + 2], e3 = list[c + 3];
        __half2 f0 = g_xh[(size_t)(e0 >> 9) * 32 + lane];
        __half2 f1 = g_xh[(size_t)(e1 >> 9) * 32 + lane];
        __half2 f2 = g_xh[(size_t)(e2 >> 9) * 32 + lane];
        __half2 f3 = g_xh[(size_t)(e3 >> 9) * 32 + lane];
        __half2 w0 = g_w1h[(e0 & 511) * 32 + lane];
        __half2 w1 = g_w1h[(e1 & 511) * 32 + lane];
        __half2 w2 = g_w1h[(e2 & 511) * 32 + lane];
        __half2 w3 = g_w1h[(e3 & 511) * 32 + lane];
        float2 p0 = __half22float2(__hmul2(f0, w0));
        float2 p1 = __half22float2(__hmul2(f1, w1));
        float2 p2 = __half22float2(__hmul2(f2, w2));
        float2 p3 = __half22float2(__hmul2(f3, w3));
        acc.x += (p0.x + p1.x) + (p2.x + p3.x);
        acc.y += (p0.y + p1.y) + (p2.y + p3.y);
    }

    float2 bb = ((const float2*)b1)[lane];
    acc.x += bb.x; acc.y += bb.y;

    float s  = acc.x + acc.y;
    float s2 = acc.x * acc.x + acc.y * acc.y;
    #pragma unroll
    for (int o = 16; o > 0; o >>= 1) {
        s  += __shfl_xor_sync(0xffffffffu, s,  o);
        s2 += __shfl_xor_sync(0xffffffffu, s2, o);
    }
    float mu  = s  * (1.f / 64.f);
    float var = s2 * (1.f / 64.f) - mu * mu;
    float inv = rsqrtf(var + 1e-5f);

    float2 g  = ((const float2*)gamma)[lane];
    float2 be = ((const float2*)beta)[lane];
    float ox = (acc.x - mu) * inv * g.x + be.x;
    float oy = (acc.y - mu) * inv * g.y + be.y;

    ((__half2*)g_hh)[(size_t)i * 32 + lane] = __floats2half2_rn(ox, oy);
}

// ---------------------------------------------------------------------------
// Kernel 2: fp16 tensor-core MLP. 128 voxels/CTA, 8 warps (16 rows each).
// Weights staged once into smem (conflict-free padded strides), LDS fragments.
// ---------------------------------------------------------------------------
#define XSTR  72    // sX row stride (halfs): banks (4g+q) all distinct
#define W2STR 72    // sW2 row stride (halfs)
#define W3STR 264   // sW3 row stride (halfs)
#define OF_X   0
#define OF_W2  18432                      // 128*72*2
#define OF_W3  (OF_W2 + 256 * W2STR * 2)  // +36864 = 55296
#define OF_B2  (OF_W3 + 64 * W3STR * 2)   // +33792 = 89088
#define OF_B3  (OF_B2 + 1024)             // 90112
#define SMEM_SZ (OF_B3 + 256)             // 90368 bytes

__global__ __launch_bounds__(256)
void mlp_f16_kernel(const float* __restrict__ x_feat,
                    const float* __restrict__ b2,
                    const float* __restrict__ b3,
                    float* __restrict__ out, int N) {
    extern __shared__ char sm[];
    __half* sX  = (__half*)(sm + OF_X);
    __half* sW2 = (__half*)(sm + OF_W2);
    __half* sW3 = (__half*)(sm + OF_W3);
    float*  sB2 = (float*)(sm + OF_B2);
    float*  sB3 = (float*)(sm + OF_B3);

    const int t  = threadIdx.x;
    const int v0 = blockIdx.x * TILE_M;

    // ---- stage X tile (fp16, zero-pad beyond N) ----
    {
        const uint4* src = (const uint4*)g_hh;
        #pragma unroll
        for (int it = 0; it < 4; ++it) {
            int idx = t + it * 256;             // 0..1023 uint4 (8 halfs each)
            int row = idx >> 3, c8 = idx & 7;
            uint4 v = make_uint4(0, 0, 0, 0);
            if (v0 + row < N) v = src[(size_t)(v0 + row) * 8 + c8];
            *(uint4*)(sX + row * XSTR + c8 * 8) = v;
        }
    }
    // ---- stage W2^T [256 rows x 64 halfs] ----
    {
        const uint4* src = (const uint4*)g_w2t;
        #pragma unroll
        for (int it = 0; it < 8; ++it) {
            int idx = t + it * 256;             // 0..2047
            int row = idx >> 3, c8 = idx & 7;
            *(uint4*)(sW2 + row * W2STR + c8 * 8) = src[idx];
        }
    }
    // ---- stage W3^T [64 rows x 256 halfs] ----
    {
        const uint4* src = (const uint4*)g_w3t;
        #pragma unroll
        for (int it = 0; it < 8; ++it) {
            int idx = t + it * 256;             // 0..2047
            int row = idx >> 5, c16 = idx & 31;
            *(uint4*)(sW3 + row * W3STR + c16 * 8) = src[idx];
        }
    }
    sB2[t] = b2[t];
    if (t < 64) sB3[t] = b3[t];
    __syncthreads();

    const int wid = t >> 5, lane = t & 31;
    const int g = lane >> 2, q = lane & 3;
    const int R0 = wid * 16;

    // ---- A fragments of GEMM1 (K=64 -> 4 k-steps of 16), loaded once ----
    uint32_t A1[4][4];
    {
        const __half* xb = sX + (R0 + g) * XSTR + 2 * q;
        #pragma unroll
        for (int ks = 0; ks < 4; ++ks) {
            A1[ks][0] = *(const uint32_t*)(xb + 16 * ks);
            A1[ks][1] = *(const uint32_t*)(xb + 16 * ks + 8 * XSTR);
            A1[ks][2] = *(const uint32_t*)(xb + 16 * ks + 8);
            A1[ks][3] = *(const uint32_t*)(xb + 16 * ks + 8 * XSTR + 8);
        }
    }

    float acc2[8][4];
    #pragma unroll
    for (int n = 0; n < 8; ++n)
        { acc2[n][0] = acc2[n][1] = acc2[n][2] = acc2[n][3] = 0.f; }

    #pragma unroll 1
    for (int ch = 0; ch < 4; ++ch) {
        const int cb = ch * 64;

        // ---- GEMM1 chunk: acc1[16 x 64] ----
        float acc1[8][4];
        #pragma unroll
        for (int n = 0; n < 8; ++n)
            { acc1[n][0] = acc1[n][1] = acc1[n][2] = acc1[n][3] = 0.f; }

        #pragma unroll
        for (int nt = 0; nt < 8; ++nt) {
            const uint32_t* wp = (const uint32_t*)(sW2 + (cb + nt * 8 + g) * W2STR) + q;
            #pragma unroll
            for (int ks = 0; ks < 4; ++ks) {
                uint32_t b0 = wp[8 * ks];
                uint32_t b1 = wp[8 * ks + 4];
                MMA_F16(acc1[nt], A1[ks], b0, b1);
            }
        }

        // ---- bias + exact GELU + pack to fp16 (= GEMM2 A fragments) ----
        uint32_t H2[8], H2B[8];
        #pragma unroll
        for (int nt = 0; nt < 8; ++nt) {
            float2 bv = *(const float2*)(sB2 + cb + nt * 8 + 2 * q);
            float g0 = gelu_exact(acc1[nt][0] + bv.x);
            float g1 = gelu_exact(acc1[nt][1] + bv.y);
            float g2 = gelu_exact(acc1[nt][2] + bv.x);
            float g3 = gelu_exact(acc1[nt][3] + bv.y);
            H2[nt]  = pack_f16x2(g0, g1);   // row g,   cols 2q,2q+1
            H2B[nt] = pack_f16x2(g2, g3);   // row g+8
        }

        // ---- GEMM2 partial: acc2 += G_chunk[128x64] @ W3[cb:cb+64, :] ----
        #pragma unroll
        for (int nt2 = 0; nt2 < 8; ++nt2) {
            const uint32_t* wp3 = (const uint32_t*)(sW3 + (nt2 * 8 + g) * W3STR + cb) + q;
            #pragma unroll
            for (int kk = 0; kk < 4; ++kk) {
                uint32_t a[4] = { H2[2 * kk], H2B[2 * kk], H2[2 * kk + 1], H2B[2 * kk + 1] };
                uint32_t b0 = wp3[8 * kk];
                uint32_t b1 = wp3[8 * kk + 4];
                MMA_F16(acc2[nt2], a, b0, b1);
            }
        }
    }

    // ---- epilogue: + b3 + residual, store ----
    {
        const int v_lo = v0 + R0 + g;
        const int v_hi = v_lo + 8;
        #pragma unroll
        for (int nt2 = 0; nt2 < 8; ++nt2) {
            int col = nt2 * 8 + 2 * q;
            float2 bv = *(const float2*)(sB3 + col);
            if (v_lo < N) {
                float2 xr = *(const float2*)(x_feat + (size_t)v_lo * 64 + col);
                float2 o;
                o.x = acc2[nt2][0] + bv.x + xr.x;
                o.y = acc2[nt2][1] + bv.y + xr.y;
                *(float2*)(out + (size_t)v_lo * 64 + col) = o;
            }
            if (v_hi < N) {
                float2 xr = *(const float2*)(x_feat + (size_t)v_hi * 64 + col);
                float2 o;
                o.x = acc2[nt2][2] + bv.x + xr.x;
                o.y = acc2[nt2][3] + bv.y + xr.y;
                *(float2*)(out + (size_t)v_hi * 64 + col) = o;
            }
        }
    }
}

// ---------------------------------------------------------------------------
extern "C" void kernel_launch(void* const* d_in, const int* in_sizes, int n_in,
                              void* d_out, int out_size) {
    const float* x_feat = (const float*)d_in[0];
    const int*   nbr    = (const int*)  d_in[1];
    const float* W1     = (const float*)d_in[2];
    const float* b1     = (const float*)d_in[3];
    const float* gamma  = (const float*)d_in[4];
    const float* beta   = (const float*)d_in[5];
    const float* W2     = (const float*)d_in[6];
    const float* b2     = (const float*)d_in[7];
    const float* W3     = (const float*)d_in[8];
    const float* b3     = (const float*)d_in[9];
    float* out = (float*)d_out;

    int N = in_sizes[0] / C;
    int tiles = (N + TILE_M - 1) / TILE_M;

    static int smem_set = 0;
    if (!smem_set) {
        cudaFuncSetAttribute(mlp_f16_kernel, cudaFuncAttributeMaxDynamicSharedMemorySize, SMEM_SZ);
        smem_set = 1;
    }

    int prep_elems = (N + 1) * 32 + KTAPS * 32 + 256 * 32 + 64 * 128;
    prep_kernel<<<(prep_elems + 255) / 256, 256>>>(x_feat, W1, W2, W3, N);

    int blocks1 = (N + DW_WARPS - 1) / DW_WARPS;
    dwconv_gn_kernel<<<blocks1, 256>>>(nbr, b1, gamma, beta, N);

    mlp_f16_kernel<<<tiles, 256, SMEM_SZ>>>(x_feat, b2, b3, out, N);
}

// round 7
// speedup vs baseline: 2.2566x; 1.3773x over previous
#include <cuda_runtime.h>
#include <cuda_fp16.h>
#include <math.h>
#include <stdint.h>

#define NMAX   100000
#define C      64
#define KTAPS  343
#define TILE_M 128

// ---------------------------------------------------------------------------
// device scratch (no cudaMalloc allowed)
// ---------------------------------------------------------------------------
__device__ __align__(16) __half2 g_xh[(size_t)(NMAX + 1) * 32]; // x_feat fp16 [N+1][64], row N = zeros
__device__ __align__(16) __half2 g_w1h[KTAPS * 32];             // W1 fp16 [343][64]
__device__ __align__(16) __half  g_hh[(size_t)NMAX * 64];       // h post-GN fp16 [N][64]
__device__ __align__(16) __half  g_w2t[256 * 64];               // W2^T: [n][k] fp16
__device__ __align__(16) __half  g_w3t[64 * 256];               // W3^T: [c][j] fp16

__device__ __forceinline__ float gelu_exact(float x) {
    return 0.5f * x * (1.f + erff(x * 0.70710678118654752f));
}
__device__ __forceinline__ uint32_t pack_f16x2(float lo, float hi) {
    uint32_t u;
    asm("cvt.rn.f16x2.f32 %0, %1, %2;" : "=r"(u) : "f"(hi), "f"(lo));
    return u;
}

// D += A * B   (m16n8k16, f16 inputs, f32 accum; A row frag, B col frag)
#define MMA_F16(d, a, b0, b1)                                                           \
    asm volatile("mma.sync.aligned.m16n8k16.row.col.f32.f16.f16.f32 "                   \
                 "{%0,%1,%2,%3}, {%4,%5,%6,%7}, {%8,%9}, {%0,%1,%2,%3};"                \
                 : "+f"((d)[0]), "+f"((d)[1]), "+f"((d)[2]), "+f"((d)[3])               \
                 : "r"((a)[0]), "r"((a)[1]), "r"((a)[2]), "r"((a)[3]),                  \
                   "r"(b0), "r"(b1))

// ---------------------------------------------------------------------------
// Kernel 0: fp16 conversions + transposed fp16 weights + zero sentinel row
// ---------------------------------------------------------------------------
__global__ void prep_kernel(const float* __restrict__ x,
                            const float* __restrict__ W1,
                            const float* __restrict__ W2,
                            const float* __restrict__ W3, int N) {
    int e = blockIdx.x * blockDim.x + threadIdx.x;
    int nx = (N + 1) * 32;
    if (e < nx) {
        if ((e >> 5) < N) {
            float2 v = ((const float2*)x)[e];
            g_xh[e] = __floats2half2_rn(v.x, v.y);
        } else {
            g_xh[e] = __floats2half2_rn(0.f, 0.f);   // sentinel row N = zeros
        }
        return;
    }
    int e1 = e - nx;
    if (e1 < KTAPS * 32) {
        float2 v = ((const float2*)W1)[e1];
        g_w1h[e1] = __floats2half2_rn(v.x, v.y);
        return;
    }
    int e2 = e1 - KTAPS * 32;
    if (e2 < 256 * 32) {                       // g_w2t[n][k] = W2[k][n]
        int n = e2 >> 5, k2 = e2 & 31;
        ((__half2*)g_w2t)[e2] =
            __floats2half2_rn(W2[(2 * k2) * 256 + n], W2[(2 * k2 + 1) * 256 + n]);
        return;
    }
    int e3 = e2 - 256 * 32;
    if (e3 < 64 * 128) {                       // g_w3t[c][j] = W3[j][c]
        int c = e3 >> 7, j2 = e3 & 127;
        ((__half2*)g_w3t)[e3] =
            __floats2half2_rn(W3[(2 * j2) * 64 + c], W3[(2 * j2 + 1) * 64 + c]);
    }
}

// ---------------------------------------------------------------------------
// Kernel 1: depthwise submanifold conv + bias + GroupNorm
// one warp per voxel; compacted tap list; 4 taps per LDG.128:
// lane = (grp = lane>>3) tap-slot, (sub = lane&7) 8-channel slice.
// ---------------------------------------------------------------------------
#define DW_WARPS 8

__device__ __forceinline__ void accum8(float* acc, uint4 f, uint4 w) {
    const __half2* fh = (const __half2*)&f;
    const __half2* wh = (const __half2*)&w;
    #pragma unroll
    for (int m = 0; m < 4; ++m) {
        float2 p = __half22float2(__hmul2(fh[m], wh[m]));
        acc[2 * m]     += p.x;
        acc[2 * m + 1] += p.y;
    }
}

__global__ __launch_bounds__(256)
void dwconv_gn_kernel(const int*   __restrict__ nbr,
                      const float* __restrict__ b1,
                      const float* __restrict__ gamma,
                      const float* __restrict__ beta,
                      int N) {
    __shared__ int s_list[DW_WARPS][352];

    const int wslot = threadIdx.x >> 5;
    const int lane  = threadIdx.x & 31;
    const int grp   = lane >> 3;     // tap slot 0..3
    const int sub   = lane & 7;      // channel slice (8 ch)
    const int i = blockIdx.x * DW_WARPS + wslot;
    if (i >= N) return;

    const int* row = nbr + (long long)i * KTAPS;
    int* list = s_list[wslot];

    // ---- phase 1: compact valid (src, tap) into smem list ----
    int cnt = 0;
    #pragma unroll
    for (int kb = 0; kb < 352; kb += 32) {
        int k = kb + lane;
        int idx = (k < KTAPS) ? row[k] : N;
        bool valid = idx < N;
        unsigned m = __ballot_sync(0xffffffffu, valid);
        if (valid) {
            int pos = cnt + __popc(m & ((1u << lane) - 1));
            list[pos] = (idx << 9) | k;
        }
        cnt += __popc(m);
    }
    int cnt8 = (cnt + 7) & ~7;
    if (lane < cnt8 - cnt) list[cnt + lane] = (N << 9);   // pad: zero row, tap 0
    __syncwarp();

    // ---- phase 2: 8 taps per iteration, 4 taps per LDG.128 ----
    const uint4* xh4 = (const uint4*)g_xh;    // [N+1][8] uint4 rows
    const uint4* w14 = (const uint4*)g_w1h;   // [343][8]

    float acc[8];
    #pragma unroll
    for (int j = 0; j < 8; ++j) acc[j] = 0.f;

    #pragma unroll 1
    for (int c = 0; c < cnt8; c += 8) {
        int e0 = list[c + grp];
        int e1 = list[c + 4 + grp];
        uint4 f0 = xh4[(size_t)(e0 >> 9) * 8 + sub];
        uint4 f1 = xh4[(size_t)(e1 >> 9) * 8 + sub];
        uint4 w0 = w14[(e0 & 511) * 8 + sub];
        uint4 w1 = w14[(e1 & 511) * 8 + sub];
        accum8(acc, f0, w0);
        accum8(acc, f1, w1);
    }

    // ---- reduce across the 4 tap groups ----
    #pragma unroll
    for (int j = 0; j < 8; ++j) {
        acc[j] += __shfl_xor_sync(0xffffffffu, acc[j], 8);
        acc[j] += __shfl_xor_sync(0xffffffffu, acc[j], 16);
    }

    // ---- bias ----
    {
        float4 ba = ((const float4*)b1)[sub * 2];
        float4 bb = ((const float4*)b1)[sub * 2 + 1];
        acc[0] += ba.x; acc[1] += ba.y; acc[2] += ba.z; acc[3] += ba.w;
        acc[4] += bb.x; acc[5] += bb.y; acc[6] += bb.z; acc[7] += bb.w;
    }

    // ---- GroupNorm over 64 channels (sum within 8-lane group) ----
    float s = 0.f, s2 = 0.f;
    #pragma unroll
    for (int j = 0; j < 8; ++j) { s += acc[j]; s2 += acc[j] * acc[j]; }
    #pragma unroll
    for (int o = 1; o < 8; o <<= 1) {
        s  += __shfl_xor_sync(0xffffffffu, s,  o);
        s2 += __shfl_xor_sync(0xffffffffu, s2, o);
    }
    float mu  = s  * (1.f / 64.f);
    float var = s2 * (1.f / 64.f) - mu * mu;
    float inv = rsqrtf(var + 1e-5f);

    float4 ga = ((const float4*)gamma)[sub * 2];
    float4 gb = ((const float4*)gamma)[sub * 2 + 1];
    float4 ea = ((const float4*)beta)[sub * 2];
    float4 eb = ((const float4*)beta)[sub * 2 + 1];

    float o0 = (acc[0] - mu) * inv * ga.x + ea.x;
    float o1 = (acc[1] - mu) * inv * ga.y + ea.y;
    float o2 = (acc[2] - mu) * inv * ga.z + ea.z;
    float o3 = (acc[3] - mu) * inv * ga.w + ea.w;
    float o4 = (acc[4] - mu) * inv * gb.x + eb.x;
    float o5 = (acc[5] - mu) * inv * gb.y + eb.y;
    float o6 = (acc[6] - mu) * inv * gb.z + eb.z;
    float o7 = (acc[7] - mu) * inv * gb.w + eb.w;

    if (grp == 0) {
        uint4 v;
        v.x = pack_f16x2(o0, o1);
        v.y = pack_f16x2(o2, o3);
        v.z = pack_f16x2(o4, o5);
        v.w = pack_f16x2(o6, o7);
        ((uint4*)g_hh)[(size_t)i * 8 + sub] = v;
    }
}

// ---------------------------------------------------------------------------
// Kernel 2: fp16 tensor-core MLP. 128 voxels/CTA, 8 warps (16 rows each).
// Weights staged once into smem (conflict-free padded strides), LDS fragments.
// ---------------------------------------------------------------------------
#define XSTR  72    // sX row stride (halfs): banks (4g+q) all distinct
#define W2STR 72    // sW2 row stride (halfs)
#define W3STR 264   // sW3 row stride (halfs)
#define OF_X   0
#define OF_W2  18432                      // 128*72*2
#define OF_W3  (OF_W2 + 256 * W2STR * 2)  // +36864 = 55296
#define OF_B2  (OF_W3 + 64 * W3STR * 2)   // +33792 = 89088
#define OF_B3  (OF_B2 + 1024)             // 90112
#define SMEM_SZ (OF_B3 + 256)             // 90368 bytes

__global__ __launch_bounds__(256)
void mlp_f16_kernel(const float* __restrict__ x_feat,
                    const float* __restrict__ b2,
                    const float* __restrict__ b3,
                    float* __restrict__ out, int N) {
    extern __shared__ char sm[];
    __half* sX  = (__half*)(sm + OF_X);
    __half* sW2 = (__half*)(sm + OF_W2);
    __half* sW3 = (__half*)(sm + OF_W3);
    float*  sB2 = (float*)(sm + OF_B2);
    float*  sB3 = (float*)(sm + OF_B3);

    const int t  = threadIdx.x;
    const int v0 = blockIdx.x * TILE_M;

    // ---- stage X tile (fp16, zero-pad beyond N) ----
    {
        const uint4* src = (const uint4*)g_hh;
        #pragma unroll
        for (int it = 0; it < 4; ++it) {
            int idx = t + it * 256;             // 0..1023 uint4 (8 halfs each)
            int row = idx >> 3, c8 = idx & 7;
            uint4 v = make_uint4(0, 0, 0, 0);
            if (v0 + row < N) v = src[(size_t)(v0 + row) * 8 + c8];
            *(uint4*)(sX + row * XSTR + c8 * 8) = v;
        }
    }
    // ---- stage W2^T [256 rows x 64 halfs] ----
    {
        const uint4* src = (const uint4*)g_w2t;
        #pragma unroll
        for (int it = 0; it < 8; ++it) {
            int idx = t + it * 256;             // 0..2047
            int row = idx >> 3, c8 = idx & 7;
            *(uint4*)(sW2 + row * W2STR + c8 * 8) = src[idx];
        }
    }
    // ---- stage W3^T [64 rows x 256 halfs] ----
    {
        const uint4* src = (const uint4*)g_w3t;
        #pragma unroll
        for (int it = 0; it < 8; ++it) {
            int idx = t + it * 256;             // 0..2047
            int row = idx >> 5, c16 = idx & 31;
            *(uint4*)(sW3 + row * W3STR + c16 * 8) = src[idx];
        }
    }
    sB2[t] = b2[t];
    if (t < 64) sB3[t] = b3[t];
    __syncthreads();

    const int wid = t >> 5, lane = t & 31;
    const int g = lane >> 2, q = lane & 3;
    const int R0 = wid * 16;

    // ---- A fragments of GEMM1 (K=64 -> 4 k-steps of 16), loaded once ----
    uint32_t A1[4][4];
    {
        const __half* xb = sX + (R0 + g) * XSTR + 2 * q;
        #pragma unroll
        for (int ks = 0; ks < 4; ++ks) {
            A1[ks][0] = *(const uint32_t*)(xb + 16 * ks);
            A1[ks][1] = *(const uint32_t*)(xb + 16 * ks + 8 * XSTR);
            A1[ks][2] = *(const uint32_t*)(xb + 16 * ks + 8);
            A1[ks][3] = *(const uint32_t*)(xb + 16 * ks + 8 * XSTR + 8);
        }
    }

    float acc2[8][4];
    #pragma unroll
    for (int n = 0; n < 8; ++n)
        { acc2[n][0] = acc2[n][1] = acc2[n][2] = acc2[n][3] = 0.f; }

    #pragma unroll 1
    for (int ch = 0; ch < 4; ++ch) {
        const int cb = ch * 64;

        // ---- GEMM1 chunk: acc1[16 x 64] ----
        float acc1[8][4];
        #pragma unroll
        for (int n = 0; n < 8; ++n)
            { acc1[n][0] = acc1[n][1] = acc1[n][2] = acc1[n][3] = 0.f; }

        #pragma unroll
        for (int nt = 0; nt < 8; ++nt) {
            const uint32_t* wp = (const uint32_t*)(sW2 + (cb + nt * 8 + g) * W2STR) + q;
            #pragma unroll
            for (int ks = 0; ks < 4; ++ks) {
                uint32_t b0 = wp[8 * ks];
                uint32_t b1 = wp[8 * ks + 4];
                MMA_F16(acc1[nt], A1[ks], b0, b1);
            }
        }

        // ---- bias + exact GELU + pack to fp16 (= GEMM2 A fragments) ----
        uint32_t H2[8], H2B[8];
        #pragma unroll
        for (int nt = 0; nt < 8; ++nt) {
            float2 bv = *(const float2*)(sB2 + cb + nt * 8 + 2 * q);
            float g0 = gelu_exact(acc1[nt][0] + bv.x);
            float g1 = gelu_exact(acc1[nt][1] + bv.y);
            float g2 = gelu_exact(acc1[nt][2] + bv.x);
            float g3 = gelu_exact(acc1[nt][3] + bv.y);
            H2[nt]  = pack_f16x2(g0, g1);   // row g,   cols 2q,2q+1
            H2B[nt] = pack_f16x2(g2, g3);   // row g+8
        }

        // ---- GEMM2 partial: acc2 += G_chunk[128x64] @ W3[cb:cb+64, :] ----
        #pragma unroll
        for (int nt2 = 0; nt2 < 8; ++nt2) {
            const uint32_t* wp3 = (const uint32_t*)(sW3 + (nt2 * 8 + g) * W3STR + cb) + q;
            #pragma unroll
            for (int kk = 0; kk < 4; ++kk) {
                uint32_t a[4] = { H2[2 * kk], H2B[2 * kk], H2[2 * kk + 1], H2B[2 * kk + 1] };
                uint32_t b0 = wp3[8 * kk];
                uint32_t b1 = wp3[8 * kk + 4];
                MMA_F16(acc2[nt2], a, b0, b1);
            }
        }
    }

    // ---- epilogue: + b3 + residual, store ----
    {
        const int v_lo = v0 + R0 + g;
        const int v_hi = v_lo + 8;
        #pragma unroll
        for (int nt2 = 0; nt2 < 8; ++nt2) {
            int col = nt2 * 8 + 2 * q;
            float2 bv = *(const float2*)(sB3 + col);
            if (v_lo < N) {
                float2 xr = *(const float2*)(x_feat + (size_t)v_lo * 64 + col);
                float2 o;
                o.x = acc2[nt2][0] + bv.x + xr.x;
                o.y = acc2[nt2][1] + bv.y + xr.y;
                *(float2*)(out + (size_t)v_lo * 64 + col) = o;
            }
            if (v_hi < N) {
                float2 xr = *(const float2*)(x_feat + (size_t)v_hi * 64 + col);
                float2 o;
                o.x = acc2[nt2][2] + bv.x + xr.x;
                o.y = acc2[nt2][3] + bv.y + xr.y;
                *(float2*)(out + (size_t)v_hi * 64 + col) = o;
            }
        }
    }
}

// ---------------------------------------------------------------------------
extern "C" void kernel_launch(void* const* d_in, const int* in_sizes, int n_in,
                              void* d_out, int out_size) {
    const float* x_feat = (const float*)d_in[0];
    const int*   nbr    = (const int*)  d_in[1];
    const float* W1     = (const float*)d_in[2];
    const float* b1     = (const float*)d_in[3];
    const float* gamma  = (const float*)d_in[4];
    const float* beta   = (const float*)d_in[5];
    const float* W2     = (const float*)d_in[6];
    const float* b2     = (const float*)d_in[7];
    const float* W3     = (const float*)d_in[8];
    const float* b3     = (const float*)d_in[9];
    float* out = (float*)d_out;

    int N = in_sizes[0] / C;
    int tiles = (N + TILE_M - 1) / TILE_M;

    static int smem_set = 0;
    if (!smem_set) {
        cudaFuncSetAttribute(mlp_f16_kernel, cudaFuncAttributeMaxDynamicSharedMemorySize, SMEM_SZ);
        smem_set = 1;
    }

    int prep_elems = (N + 1) * 32 + KTAPS * 32 + 256 * 32 + 64 * 128;
    prep_kernel<<<(prep_elems + 255) / 256, 256>>>(x_feat, W1, W2, W3, N);

    int blocks1 = (N + DW_WARPS - 1) / DW_WARPS;
    dwconv_gn_kernel<<<blocks1, 256>>>(nbr, b1, gamma, beta, N);

    mlp_f16_kernel<<<tiles, 256, SMEM_SZ>>>(x_feat, b2, b3, out, N);
}

// round 8
// speedup vs baseline: 2.5716x; 1.1396x over previous
#include <cuda_runtime.h>
#include <cuda_fp16.h>
#include <math.h>
#include <stdint.h>

#define NMAX   100000
#define C      64
#define KTAPS  343
#define TILE_M 128

// ---------------------------------------------------------------------------
// device scratch (no cudaMalloc allowed)
// ---------------------------------------------------------------------------
__device__ __align__(16) __half2 g_xh[(size_t)(NMAX + 1) * 32]; // x_feat fp16 [N+1][64], row N = zeros
__device__ __align__(16) __half2 g_w1h[KTAPS * 32];             // W1 fp16 [343][64]
__device__ __align__(16) __half  g_hh[(size_t)NMAX * 64];       // h post-GN fp16 [N][64]
__device__ __align__(16) __half  g_w2t[256 * 64];               // W2^T: [n][k] fp16
__device__ __align__(16) __half  g_w3t[64 * 256];               // W3^T: [c][j] fp16

__device__ __forceinline__ uint32_t pack_f16x2(float lo, float hi) {
    uint32_t u;
    asm("cvt.rn.f16x2.f32 %0, %1, %2;" : "=r"(u) : "f"(hi), "f"(lo));
    return u;
}

// tanh-form GELU with single-MUFU tanh.approx (6 instr vs ~20 for erff)
__device__ __forceinline__ float gelu_fast(float x) {
    float x2 = x * x;
    float u  = fmaf(0.035677408136f, x2, 0.7978845608028654f); // 0.7978845608*(1+0.044715x^2)
    float ta = x * u;
    float t;
    asm("tanh.approx.f32 %0, %1;" : "=f"(t) : "f"(ta));
    float hx = 0.5f * x;
    return fmaf(hx, t, hx);
}

// D += A * B   (m16n8k16, f16 inputs, f32 accum; A row frag, B col frag)
#define MMA_F16(d, a, b0, b1)                                                           \
    asm volatile("mma.sync.aligned.m16n8k16.row.col.f32.f16.f16.f32 "                   \
                 "{%0,%1,%2,%3}, {%4,%5,%6,%7}, {%8,%9}, {%0,%1,%2,%3};"                \
                 : "+f"((d)[0]), "+f"((d)[1]), "+f"((d)[2]), "+f"((d)[3])               \
                 : "r"((a)[0]), "r"((a)[1]), "r"((a)[2]), "r"((a)[3]),                  \
                   "r"(b0), "r"(b1))

// ---------------------------------------------------------------------------
// Kernel 0: fp16 conversions (uint4 granularity) + transposed fp16 weights
// ---------------------------------------------------------------------------
__global__ void prep_kernel(const float* __restrict__ x,
                            const float* __restrict__ W1,
                            const float* __restrict__ W2,
                            const float* __restrict__ W3, int N) {
    int e = blockIdx.x * blockDim.x + threadIdx.x;
    int nx = (N + 1) * 8;                       // uint4 outputs for x (+ sentinel row)
    if (e < nx) {
        uint4 v = make_uint4(0, 0, 0, 0);
        if ((e >> 3) < N) {
            const float4* s = (const float4*)x + (size_t)e * 2;
            float4 a = s[0], b = s[1];
            v.x = pack_f16x2(a.x, a.y); v.y = pack_f16x2(a.z, a.w);
            v.z = pack_f16x2(b.x, b.y); v.w = pack_f16x2(b.z, b.w);
        }
        ((uint4*)g_xh)[e] = v;
        return;
    }
    int e1 = e - nx;
    if (e1 < KTAPS * 8) {
        const float4* s = (const float4*)W1 + (size_t)e1 * 2;
        float4 a = s[0], b = s[1];
        uint4 v;
        v.x = pack_f16x2(a.x, a.y); v.y = pack_f16x2(a.z, a.w);
        v.z = pack_f16x2(b.x, b.y); v.w = pack_f16x2(b.z, b.w);
        ((uint4*)g_w1h)[e1] = v;
        return;
    }
    int e2 = e1 - KTAPS * 8;
    if (e2 < 256 * 32) {                       // g_w2t[n][k] = W2[k][n]
        int n = e2 >> 5, k2 = e2 & 31;
        ((__half2*)g_w2t)[e2] =
            __floats2half2_rn(W2[(2 * k2) * 256 + n], W2[(2 * k2 + 1) * 256 + n]);
        return;
    }
    int e3 = e2 - 256 * 32;
    if (e3 < 64 * 128) {                       // g_w3t[c][j] = W3[j][c]
        int c = e3 >> 7, j2 = e3 & 127;
        ((__half2*)g_w3t)[e3] =
            __floats2half2_rn(W3[(2 * j2) * 64 + c], W3[(2 * j2 + 1) * 64 + c]);
    }
}

// ---------------------------------------------------------------------------
// Kernel 1: depthwise submanifold conv + bias + GroupNorm
// one warp per voxel; compacted tap list; 4 taps per LDG.128:
// lane = (grp = lane>>3) tap-slot, (sub = lane&7) 8-channel slice.
// ---------------------------------------------------------------------------
#define DW_WARPS 8

__device__ __forceinline__ void accum8(float* acc, uint4 f, uint4 w) {
    const __half2* fh = (const __half2*)&f;
    const __half2* wh = (const __half2*)&w;
    #pragma unroll
    for (int m = 0; m < 4; ++m) {
        float2 p = __half22float2(__hmul2(fh[m], wh[m]));
        acc[2 * m]     += p.x;
        acc[2 * m + 1] += p.y;
    }
}

__global__ __launch_bounds__(256)
void dwconv_gn_kernel(const int*   __restrict__ nbr,
                      const float* __restrict__ b1,
                      const float* __restrict__ gamma,
                      const float* __restrict__ beta,
                      int N) {
    __shared__ int s_list[DW_WARPS][352];

    const int wslot = threadIdx.x >> 5;
    const int lane  = threadIdx.x & 31;
    const int grp   = lane >> 3;     // tap slot 0..3
    const int sub   = lane & 7;      // channel slice (8 ch)
    const int i = blockIdx.x * DW_WARPS + wslot;
    if (i >= N) return;

    const int* row = nbr + (long long)i * KTAPS;
    int* list = s_list[wslot];

    // ---- phase 1: compact valid (src, tap) into smem list ----
    int cnt = 0;
    #pragma unroll
    for (int kb = 0; kb < 352; kb += 32) {
        int k = kb + lane;
        int idx = (k < KTAPS) ? row[k] : N;
        bool valid = idx < N;
        unsigned m = __ballot_sync(0xffffffffu, valid);
        if (valid) {
            int pos = cnt + __popc(m & ((1u << lane) - 1));
            list[pos] = (idx << 9) | k;
        }
        cnt += __popc(m);
    }
    int cnt8 = (cnt + 7) & ~7;
    if (lane < cnt8 - cnt) list[cnt + lane] = (N << 9);   // pad: zero row, tap 0
    __syncwarp();

    // ---- phase 2: 8 taps per iteration, 4 taps per LDG.128 ----
    const uint4* xh4 = (const uint4*)g_xh;    // [N+1][8] uint4 rows
    const uint4* w14 = (const uint4*)g_w1h;   // [343][8]

    float acc[8];
    #pragma unroll
    for (int j = 0; j < 8; ++j) acc[j] = 0.f;

    #pragma unroll 1
    for (int c = 0; c < cnt8; c += 8) {
        int e0 = list[c + grp];
        int e1 = list[c + 4 + grp];
        uint4 f0 = xh4[(size_t)(e0 >> 9) * 8 + sub];
        uint4 f1 = xh4[(size_t)(e1 >> 9) * 8 + sub];
        uint4 w0 = w14[(e0 & 511) * 8 + sub];
        uint4 w1 = w14[(e1 & 511) * 8 + sub];
        accum8(acc, f0, w0);
        accum8(acc, f1, w1);
    }

    // ---- reduce across the 4 tap groups ----
    #pragma unroll
    for (int j = 0; j < 8; ++j) {
        acc[j] += __shfl_xor_sync(0xffffffffu, acc[j], 8);
        acc[j] += __shfl_xor_sync(0xffffffffu, acc[j], 16);
    }

    // ---- bias ----
    {
        float4 ba = ((const float4*)b1)[sub * 2];
        float4 bb = ((const float4*)b1)[sub * 2 + 1];
        acc[0] += ba.x; acc[1] += ba.y; acc[2] += ba.z; acc[3] += ba.w;
        acc[4] += bb.x; acc[5] += bb.y; acc[6] += bb.z; acc[7] += bb.w;
    }

    // ---- GroupNorm over 64 channels (sum within 8-lane group) ----
    float s = 0.f, s2 = 0.f;
    #pragma unroll
    for (int j = 0; j < 8; ++j) { s += acc[j]; s2 += acc[j] * acc[j]; }
    #pragma unroll
    for (int o = 1; o < 8; o <<= 1) {
        s  += __shfl_xor_sync(0xffffffffu, s,  o);
        s2 += __shfl_xor_sync(0xffffffffu, s2, o);
    }
    float mu  = s  * (1.f / 64.f);
    float var = s2 * (1.f / 64.f) - mu * mu;
    float inv = rsqrtf(var + 1e-5f);

    float4 ga = ((const float4*)gamma)[sub * 2];
    float4 gb = ((const float4*)gamma)[sub * 2 + 1];
    float4 ea = ((const float4*)beta)[sub * 2];
    float4 eb = ((const float4*)beta)[sub * 2 + 1];

    float o0 = (acc[0] - mu) * inv * ga.x + ea.x;
    float o1 = (acc[1] - mu) * inv * ga.y + ea.y;
    float o2 = (acc[2] - mu) * inv * ga.z + ea.z;
    float o3 = (acc[3] - mu) * inv * ga.w + ea.w;
    float o4 = (acc[4] - mu) * inv * gb.x + eb.x;
    float o5 = (acc[5] - mu) * inv * gb.y + eb.y;
    float o6 = (acc[6] - mu) * inv * gb.z + eb.z;
    float o7 = (acc[7] - mu) * inv * gb.w + eb.w;

    if (grp == 0) {
        uint4 v;
        v.x = pack_f16x2(o0, o1);
        v.y = pack_f16x2(o2, o3);
        v.z = pack_f16x2(o4, o5);
        v.w = pack_f16x2(o6, o7);
        ((uint4*)g_hh)[(size_t)i * 8 + sub] = v;
    }
}

// ---------------------------------------------------------------------------
// Kernel 2: fp16 tensor-core MLP. 128 voxels/CTA, 8 warps (16 rows each).
// Weights staged once into smem (conflict-free padded strides), LDS fragments.
// ---------------------------------------------------------------------------
#define XSTR  72    // sX row stride (halfs): banks (4g+q) all distinct
#define W2STR 72    // sW2 row stride (halfs)
#define W3STR 264   // sW3 row stride (halfs)
#define OF_X   0
#define OF_W2  18432                      // 128*72*2
#define OF_W3  (OF_W2 + 256 * W2STR * 2)  // +36864 = 55296
#define OF_B2  (OF_W3 + 64 * W3STR * 2)   // +33792 = 89088
#define OF_B3  (OF_B2 + 1024)             // 90112
#define SMEM_SZ (OF_B3 + 256)             // 90368 bytes

__global__ __launch_bounds__(256)
void mlp_f16_kernel(const float* __restrict__ x_feat,
                    const float* __restrict__ b2,
                    const float* __restrict__ b3,
                    float* __restrict__ out, int N) {
    extern __shared__ char sm[];
    __half* sX  = (__half*)(sm + OF_X);
    __half* sW2 = (__half*)(sm + OF_W2);
    __half* sW3 = (__half*)(sm + OF_W3);
    float*  sB2 = (float*)(sm + OF_B2);
    float*  sB3 = (float*)(sm + OF_B3);

    const int t  = threadIdx.x;
    const int v0 = blockIdx.x * TILE_M;

    // ---- stage X tile (fp16, zero-pad beyond N) ----
    {
        const uint4* src = (const uint4*)g_hh;
        #pragma unroll
        for (int it = 0; it < 4; ++it) {
            int idx = t + it * 256;             // 0..1023 uint4 (8 halfs each)
            int row = idx >> 3, c8 = idx & 7;
            uint4 v = make_uint4(0, 0, 0, 0);
            if (v0 + row < N) v = src[(size_t)(v0 + row) * 8 + c8];
            *(uint4*)(sX + row * XSTR + c8 * 8) = v;
        }
    }
    // ---- stage W2^T [256 rows x 64 halfs] ----
    {
        const uint4* src = (const uint4*)g_w2t;
        #pragma unroll
        for (int it = 0; it < 8; ++it) {
            int idx = t + it * 256;             // 0..2047
            int row = idx >> 3, c8 = idx & 7;
            *(uint4*)(sW2 + row * W2STR + c8 * 8) = src[idx];
        }
    }
    // ---- stage W3^T [64 rows x 256 halfs] ----
    {
        const uint4* src = (const uint4*)g_w3t;
        #pragma unroll
        for (int it = 0; it < 8; ++it) {
            int idx = t + it * 256;             // 0..2047
            int row = idx >> 5, c16 = idx & 31;
            *(uint4*)(sW3 + row * W3STR + c16 * 8) = src[idx];
        }
    }
    sB2[t] = b2[t];
    if (t < 64) sB3[t] = b3[t];
    __syncthreads();

    const int wid = t >> 5, lane = t & 31;
    const int g = lane >> 2, q = lane & 3;
    const int R0 = wid * 16;

    // ---- A fragments of GEMM1 (K=64 -> 4 k-steps of 16), loaded once ----
    uint32_t A1[4][4];
    {
        const __half* xb = sX + (R0 + g) * XSTR + 2 * q;
        #pragma unroll
        for (int ks = 0; ks < 4; ++ks) {
            A1[ks][0] = *(const uint32_t*)(xb + 16 * ks);
            A1[ks][1] = *(const uint32_t*)(xb + 16 * ks + 8 * XSTR);
            A1[ks][2] = *(const uint32_t*)(xb + 16 * ks + 8);
            A1[ks][3] = *(const uint32_t*)(xb + 16 * ks + 8 * XSTR + 8);
        }
    }

    float acc2[8][4];
    #pragma unroll
    for (int n = 0; n < 8; ++n)
        { acc2[n][0] = acc2[n][1] = acc2[n][2] = acc2[n][3] = 0.f; }

    #pragma unroll 1
    for (int ch = 0; ch < 4; ++ch) {
        const int cb = ch * 64;

        // ---- GEMM1 chunk: acc1[16 x 64] ----
        float acc1[8][4];
        #pragma unroll
        for (int n = 0; n < 8; ++n)
            { acc1[n][0] = acc1[n][1] = acc1[n][2] = acc1[n][3] = 0.f; }

        #pragma unroll
        for (int nt = 0; nt < 8; ++nt) {
            const uint32_t* wp = (const uint32_t*)(sW2 + (cb + nt * 8 + g) * W2STR) + q;
            #pragma unroll
            for (int ks = 0; ks < 4; ++ks) {
                uint32_t b0 = wp[8 * ks];
                uint32_t b1 = wp[8 * ks + 4];
                MMA_F16(acc1[nt], A1[ks], b0, b1);
            }
        }

        // ---- bias + fast GELU + pack to fp16 (= GEMM2 A fragments) ----
        uint32_t H2[8], H2B[8];
        #pragma unroll
        for (int nt = 0; nt < 8; ++nt) {
            float2 bv = *(const float2*)(sB2 + cb + nt * 8 + 2 * q);
            float g0 = gelu_fast(acc1[nt][0] + bv.x);
            float g1 = gelu_fast(acc1[nt][1] + bv.y);
            float g2 = gelu_fast(acc1[nt][2] + bv.x);
            float g3 = gelu_fast(acc1[nt][3] + bv.y);
            H2[nt]  = pack_f16x2(g0, g1);   // row g,   cols 2q,2q+1
            H2B[nt] = pack_f16x2(g2, g3);   // row g+8
        }

        // ---- GEMM2 partial: acc2 += G_chunk[128x64] @ W3[cb:cb+64, :] ----
        #pragma unroll
        for (int nt2 = 0; nt2 < 8; ++nt2) {
            const uint32_t* wp3 = (const uint32_t*)(sW3 + (nt2 * 8 + g) * W3STR + cb) + q;
            #pragma unroll
            for (int kk = 0; kk < 4; ++kk) {
                uint32_t a[4] = { H2[2 * kk], H2B[2 * kk], H2[2 * kk + 1], H2B[2 * kk + 1] };
                uint32_t b0 = wp3[8 * kk];
                uint32_t b1 = wp3[8 * kk + 4];
                MMA_F16(acc2[nt2], a, b0, b1);
            }
        }
    }

    // ---- epilogue: + b3 + residual, store ----
    {
        const int v_lo = v0 + R0 + g;
        const int v_hi = v_lo + 8;
        #pragma unroll
        for (int nt2 = 0; nt2 < 8; ++nt2) {
            int col = nt2 * 8 + 2 * q;
            float2 bv = *(const float2*)(sB3 + col);
            if (v_lo < N) {
                float2 xr = *(const float2*)(x_feat + (size_t)v_lo * 64 + col);
                float2 o;
                o.x = acc2[nt2][0] + bv.x + xr.x;
                o.y = acc2[nt2][1] + bv.y + xr.y;
                *(float2*)(out + (size_t)v_lo * 64 + col) = o;
            }
            if (v_hi < N) {
                float2 xr = *(const float2*)(x_feat + (size_t)v_hi * 64 + col);
                float2 o;
                o.x = acc2[nt2][2] + bv.x + xr.x;
                o.y = acc2[nt2][3] + bv.y + xr.y;
                *(float2*)(out + (size_t)v_hi * 64 + col) = o;
            }
        }
    }
}

// ---------------------------------------------------------------------------
extern "C" void kernel_launch(void* const* d_in, const int* in_sizes, int n_in,
                              void* d_out, int out_size) {
    const float* x_feat = (const float*)d_in[0];
    const int*   nbr    = (const int*)  d_in[1];
    const float* W1     = (const float*)d_in[2];
    const float* b1     = (const float*)d_in[3];
    const float* gamma  = (const float*)d_in[4];
    const float* beta   = (const float*)d_in[5];
    const float* W2     = (const float*)d_in[6];
    const float* b2     = (const float*)d_in[7];
    const float* W3     = (const float*)d_in[8];
    const float* b3     = (const float*)d_in[9];
    float* out = (float*)d_out;

    int N = in_sizes[0] / C;
    int tiles = (N + TILE_M - 1) / TILE_M;

    static int smem_set = 0;
    if (!smem_set) {
        cudaFuncSetAttribute(mlp_f16_kernel, cudaFuncAttributeMaxDynamicSharedMemorySize, SMEM_SZ);
        smem_set = 1;
    }

    int prep_elems = (N + 1) * 8 + KTAPS * 8 + 256 * 32 + 64 * 128;
    prep_kernel<<<(prep_elems + 255) / 256, 256>>>(x_feat, W1, W2, W3, N);

    int blocks1 = (N + DW_WARPS - 1) / DW_WARPS;
    dwconv_gn_kernel<<<blocks1, 256>>>(nbr, b1, gamma, beta, N);

    mlp_f16_kernel<<<tiles, 256, SMEM_SZ>>>(x_feat, b2, b3, out, N);
}